// round 15
// baseline (speedup 1.0000x reference)
#include <cuda_runtime.h>
#include <cuda_bf16.h>
#include <cstdint>

#define B    8
#define NN   2048
#define FIN  128
#define FOUT 64

// Scratch (no cudaMalloc allowed)
__device__ __align__(16) __nv_bfloat16 g_Vth[B * FOUT * NN];  // [b][n][j] hi
__device__ __align__(16) __nv_bfloat16 g_Vtl[B * FOUT * NN];  // [b][n][j] lo
__device__ __align__(16) float    g_s1[B * NN];
__device__ __align__(16) float    g_s2[B * NN];
__device__ __align__(16) float2   g_e1[B * NN];               // (exp(s1), exp(.2 s1))
__device__ __align__(16) float2   g_e2[B * NN];               // (exp(s2), exp(.2 s2))
__device__ __align__(16) float    g_pC[2 * B * NN * FOUT];    // partial C
__device__ __align__(16) float    g_pd[2 * B * NN];           // partial denom

// ---------------------------------------------------------------------------
__device__ __forceinline__ float fexp(float x) {   // FMA-pipe exp, rel ~2e-6
    float z  = fmaf(x, 1.4426950408889634f, 12582912.0f);
    int   n  = __float_as_int(z) - 0x4B400000;
    float zf = z - 12582912.0f;
    float r  = fmaf(zf, -0.6931471805599453f, x);
    float p  =        1.3888889e-3f;
    p = fmaf(p, r,    8.3333333e-3f);
    p = fmaf(p, r,    4.1666668e-2f);
    p = fmaf(p, r,    1.6666667e-1f);
    p = fmaf(p, r,    5.0000000e-1f);
    p = fmaf(p, r,    1.0f);
    p = fmaf(p, r,    1.0f);
    return __int_as_float(__float_as_int(p) + (n << 23));
}

__device__ __forceinline__ uint32_t b2u(__nv_bfloat162 v) {
    return *reinterpret_cast<uint32_t*>(&v);
}
__device__ __forceinline__ void split2(float x0, float x1,
                                       uint32_t& hi, uint32_t& lo) {
    __nv_bfloat162 h = __floats2bfloat162_rn(x0, x1);
    float r0 = x0 - __bfloat162float(h.x);
    float r1 = x1 - __bfloat162float(h.y);
    hi = b2u(h);
    lo = b2u(__floats2bfloat162_rn(r0, r1));
}
__device__ __forceinline__ void splitT(float p0, float p1,
                                       uint32_t& hi, uint32_t& lo) {
    uint32_t i0 = __float_as_uint(p0), i1 = __float_as_uint(p1);
    float r0 = p0 - __uint_as_float(i0 & 0xffff0000u);
    float r1 = p1 - __uint_as_float(i1 & 0xffff0000u);
    asm("prmt.b32 %0, %1, %2, 0x7632;" : "=r"(hi) : "r"(i0), "r"(i1));
    lo = b2u(__floats2bfloat162_rn(r0, r1));
}
__device__ __forceinline__ float pcm(float s1, float e1p, float e1n,
                                     float s2, float e2p, float e2n, int m) {
    float t = s1 + s2;
    float p = (t > 0.f) ? e1p * e2p : e1n * e2n;
    return m ? p : 0.f;
}
__device__ __forceinline__ void mma16816(float* c, const uint32_t* a,
                                         uint32_t b0, uint32_t b1) {
    asm volatile(
        "mma.sync.aligned.m16n8k16.row.col.f32.bf16.bf16.f32 "
        "{%0,%1,%2,%3}, {%4,%5,%6,%7}, {%8,%9}, {%0,%1,%2,%3};"
        : "+f"(c[0]), "+f"(c[1]), "+f"(c[2]), "+f"(c[3])
        : "r"(a[0]), "r"(a[1]), "r"(a[2]), "r"(a[3]), "r"(b0), "r"(b1));
}
__device__ __forceinline__ void ldsm4(uint32_t& r0, uint32_t& r1,
                                      uint32_t& r2, uint32_t& r3, uint32_t a) {
    asm volatile("ldmatrix.sync.aligned.m8n8.x4.shared.b16 {%0,%1,%2,%3}, [%4];"
                 : "=r"(r0), "=r"(r1), "=r"(r2), "=r"(r3) : "r"(a));
}
__device__ __forceinline__ uint32_t smem_u32(const void* p) {
    uint32_t a;
    asm("{ .reg .u64 t; cvta.to.shared.u64 t, %1; cvt.u32.u64 %0, t; }"
        : "=r"(a) : "l"(p));
    return a;
}
#define CP16(dst, src) asm volatile("cp.async.cg.shared.global [%0], [%1], 16;" :: "r"(dst), "l"(src) : "memory")
#define CP8(dst, src)  asm volatile("cp.async.ca.shared.global [%0], [%1], 8;"  :: "r"(dst), "l"(src) : "memory")
#define CP_COMMIT()    asm volatile("cp.async.commit_group;" ::: "memory")
#define CP_WAIT0()     asm volatile("cp.async.wait_group 0;" ::: "memory")
#define CP_WAIT1()     asm volatile("cp.async.wait_group 1;" ::: "memory")

// ---------------------------------------------------------------------------
// Kernel 1: Wh = h @ W^T, fused s1/s2 (+ exp tables), transposed bf16 hi/lo V.
// (unchanged — protect)
// ---------------------------------------------------------------------------
__global__ __launch_bounds__(256) void wh_kernel(const float* __restrict__ h,
                                                 const float* __restrict__ W,
                                                 const float* __restrict__ a) {
    __shared__ float Wt[FIN][68];
    __shared__ float Tr[64][33];
    int tid = threadIdx.x;
    for (int idx = tid; idx < FOUT * FIN; idx += 256) {
        int o = idx >> 7, f = idx & 127;
        Wt[f][o] = W[idx];
    }
    __syncthreads();

    int row0 = blockIdx.x * 32;
    int rg = tid >> 4, cg = tid & 15;
    int r0 = row0 + rg * 2;
    int c0 = cg * 4;

    float acc[2][4] = {};
    const float* hp = h + (size_t)r0 * FIN;
    float4 hc0 = __ldg((const float4*)hp);
    float4 hc1 = __ldg((const float4*)(hp + FIN));
#pragma unroll 4
    for (int f = 0; f < FIN; f += 4) {
        float4 hn0, hn1;
        if (f + 4 < FIN) {
            hn0 = __ldg((const float4*)(hp + f + 4));
            hn1 = __ldg((const float4*)(hp + FIN + f + 4));
        }
        float4 wv0 = *(const float4*)&Wt[f + 0][c0];
        float4 wv1 = *(const float4*)&Wt[f + 1][c0];
        float4 wv2 = *(const float4*)&Wt[f + 2][c0];
        float4 wv3 = *(const float4*)&Wt[f + 3][c0];
        acc[0][0] += hc0.x * wv0.x + hc0.y * wv1.x + hc0.z * wv2.x + hc0.w * wv3.x;
        acc[0][1] += hc0.x * wv0.y + hc0.y * wv1.y + hc0.z * wv2.y + hc0.w * wv3.y;
        acc[0][2] += hc0.x * wv0.z + hc0.y * wv1.z + hc0.z * wv2.z + hc0.w * wv3.z;
        acc[0][3] += hc0.x * wv0.w + hc0.y * wv1.w + hc0.z * wv2.w + hc0.w * wv3.w;
        acc[1][0] += hc1.x * wv0.x + hc1.y * wv1.x + hc1.z * wv2.x + hc1.w * wv3.x;
        acc[1][1] += hc1.x * wv0.y + hc1.y * wv1.y + hc1.z * wv2.y + hc1.w * wv3.y;
        acc[1][2] += hc1.x * wv0.z + hc1.y * wv1.z + hc1.z * wv2.z + hc1.w * wv3.z;
        acc[1][3] += hc1.x * wv0.w + hc1.y * wv1.w + hc1.z * wv2.w + hc1.w * wv3.w;
        hc0 = hn0; hc1 = hn1;
    }
    __syncthreads();

    float a1x = __ldg(&a[c0]),          a1y = __ldg(&a[c0 + 1]);
    float a1z = __ldg(&a[c0 + 2]),      a1w = __ldg(&a[c0 + 3]);
    float a2x = __ldg(&a[64 + c0]),     a2y = __ldg(&a[64 + c0 + 1]);
    float a2z = __ldg(&a[64 + c0 + 2]), a2w = __ldg(&a[64 + c0 + 3]);

#pragma unroll
    for (int k = 0; k < 2; k++) {
        float t1 = acc[k][0] * a1x + acc[k][1] * a1y + acc[k][2] * a1z + acc[k][3] * a1w;
        float t2 = acc[k][0] * a2x + acc[k][1] * a2y + acc[k][2] * a2z + acc[k][3] * a2w;
#pragma unroll
        for (int ofs = 8; ofs >= 1; ofs >>= 1) {
            t1 += __shfl_xor_sync(0xffffffffu, t1, ofs);
            t2 += __shfl_xor_sync(0xffffffffu, t2, ofs);
        }
        if (cg == 0) {
            g_s1[r0 + k] = t1;
            g_s2[r0 + k] = t2;
            g_e1[r0 + k] = make_float2(fexp(t1), fexp(0.2f * t1));
            g_e2[r0 + k] = make_float2(fexp(t2), fexp(0.2f * t2));
        }
#pragma unroll
        for (int q = 0; q < 4; q++) Tr[c0 + q][rg * 2 + k] = acc[k][q];
    }
    __syncthreads();

    {
        int c  = tid >> 2;
        int jl = (tid & 3) * 8;
        int bb = row0 >> 11;
        int jb = row0 & 2047;
        float v[8];
#pragma unroll
        for (int q = 0; q < 8; q++) v[q] = Tr[c][jl + q];
        uint32_t hu[4], lu[4];
#pragma unroll
        for (int q = 0; q < 4; q++)
            split2(v[2 * q], v[2 * q + 1], hu[q], lu[q]);
        size_t dst = ((size_t)bb * 64 + c) * NN + jb + jl;
        *(uint4*)(g_Vth + dst) = make_uint4(hu[0], hu[1], hu[2], hu[3]);
        *(uint4*)(g_Vtl + dst) = make_uint4(lu[0], lu[1], lu[2], lu[3]);
    }
}

// ---------------------------------------------------------------------------
// Kernel 2: attention partial, adj + V streamed via 3-DEEP cp.async pipeline
// (wait_group 1 -> ~2 tiles of compute to hide DRAM latency).
// e2/s2 tables read via __ldg (L1-resident) — no smem tables.
// smem/CTA = 3*(2*5120 + 8704) = 56832 -> 4 CTAs/SM, single wave.
// ---------------------------------------------------------------------------
#define PVH(buf)  ((buf) * 5120)               // 64 rows x 80B
#define PVL(buf)  (15360 + (buf) * 5120)
#define PADJ(buf) (30720 + (buf) * 8704)       // 64 rows x 136B
#define P_TOTAL   56832

__global__ __launch_bounds__(128, 4) void attn_kernel(const int* __restrict__ adj) {
    extern __shared__ __align__(16) char sm[];
    uint32_t sb = smem_u32(sm);

    int tid  = threadIdx.x;
    int w    = tid >> 5;
    int lane = tid & 31;
    int g    = lane >> 2;
    int t    = lane & 3;
    int b    = blockIdx.y;
    int i0   = blockIdx.x * 64;
    int jh   = blockIdx.z;

    int    ilg = w * 16 + g;
    float  s1g  = g_s1[b * NN + i0 + ilg];
    float  s1g8 = g_s1[b * NN + i0 + ilg + 8];
    float2 e1g  = g_e1[b * NN + i0 + ilg];
    float2 e1g8 = g_e1[b * NN + i0 + ilg + 8];

    const __nv_bfloat16* vhb = g_Vth + (size_t)b * 64 * NN + jh * 1024;
    const __nv_bfloat16* vlb = g_Vtl + (size_t)b * 64 * NN + jh * 1024;
    const int*           ajb = adj + ((size_t)(b * NN + i0)) * NN + jh * 1024;
    const float*         s2b = g_s2 + b * NN + jh * 1024;
    const float*         e2b = (const float*)(g_e2 + b * NN + jh * 1024);

    uint32_t lsm_off = (((lane >> 4) & 1) * 8 + (lane & 7)) * 80
                     + ((lane >> 3) & 1) * 16;

    float C[8][4] = {};
    float part_g = 0.f, part_g8 = 0.f;

    // tile issuer: V in 16B chunks (stride 80), adj in 8B chunks (stride 136)
    auto issue_tile = [&](int it) {
        int buf = it % 3;
        int jn  = it * 32;
#pragma unroll
        for (int q = 0; q < 2; q++) {
            int c = tid + q * 128;
            int r = c >> 2, kc = c & 3;
            CP16(sb + PVH(buf) + r * 80 + kc * 16, vhb + (size_t)r * NN + jn + kc * 8);
            CP16(sb + PVL(buf) + r * 80 + kc * 16, vlb + (size_t)r * NN + jn + kc * 8);
        }
#pragma unroll
        for (int q = 0; q < 8; q++) {
            int c = tid + q * 128;
            int r = c >> 4, kc = c & 15;
            CP8(sb + PADJ(buf) + r * 136 + kc * 8, ajb + (size_t)r * NN + jn + kc * 2);
        }
        CP_COMMIT();
    };

    // prologue: tiles 0, 1 in flight
    issue_tile(0);
    issue_tile(1);

    for (int it = 0; it < 32; ++it) {
        int buf = it % 3;
        int j0  = it * 32;

        if (it >= 30) { CP_WAIT0(); } else { CP_WAIT1(); }   // tile it ready
        __syncthreads();

        if (it + 2 < 32) issue_tile(it + 2);

        // ---- stage 1: P A-fragments (tables via __ldg, mask from smem) ----
        uint32_t aH[2][4], aL[2][4];
        const char* ab = sm + PADJ(buf);
#pragma unroll
        for (int ks = 0; ks < 2; ks++) {
            int jl = ks * 16 + 2 * t;
            int jb = j0 + jl;
            int2 m0 = *(const int2*)(ab + ilg * 136 + jl * 4);
            int2 m1 = *(const int2*)(ab + ilg * 136 + (jl + 8) * 4);
            int2 m2 = *(const int2*)(ab + (ilg + 8) * 136 + jl * 4);
            int2 m3 = *(const int2*)(ab + (ilg + 8) * 136 + (jl + 8) * 4);
            float2 sA = __ldg((const float2*)(s2b + jb));
            float2 sB = __ldg((const float2*)(s2b + jb + 8));
            float4 eA = __ldg((const float4*)(e2b + 2 * jb));
            float4 eB = __ldg((const float4*)(e2b + 2 * (jb + 8)));

            float p00 = pcm(s1g,  e1g.x,  e1g.y,  sA.x, eA.x, eA.y, m0.x);
            float p01 = pcm(s1g,  e1g.x,  e1g.y,  sA.y, eA.z, eA.w, m0.y);
            float p02 = pcm(s1g,  e1g.x,  e1g.y,  sB.x, eB.x, eB.y, m1.x);
            float p03 = pcm(s1g,  e1g.x,  e1g.y,  sB.y, eB.z, eB.w, m1.y);
            float p10 = pcm(s1g8, e1g8.x, e1g8.y, sA.x, eA.x, eA.y, m2.x);
            float p11 = pcm(s1g8, e1g8.x, e1g8.y, sA.y, eA.z, eA.w, m2.y);
            float p12 = pcm(s1g8, e1g8.x, e1g8.y, sB.x, eB.x, eB.y, m3.x);
            float p13 = pcm(s1g8, e1g8.x, e1g8.y, sB.y, eB.z, eB.w, m3.y);

            part_g  += (p00 + p01) + (p02 + p03);
            part_g8 += (p10 + p11) + (p12 + p13);

            splitT(p00, p01, aH[ks][0], aL[ks][0]);
            splitT(p10, p11, aH[ks][1], aL[ks][1]);
            splitT(p02, p03, aH[ks][2], aL[ks][2]);
            splitT(p12, p13, aH[ks][3], aL[ks][3]);
        }

        // ---- MMAs, term-major ----
        uint32_t baseH = sb + PVH(buf) + lsm_off;
        uint32_t baseL = sb + PVL(buf) + lsm_off;
#pragma unroll
        for (int ks = 0; ks < 2; ks++) {
            uint32_t bf[4][4];
#pragma unroll
            for (int p = 0; p < 4; p++)
                ldsm4(bf[p][0], bf[p][1], bf[p][2], bf[p][3],
                      baseH + p * 1280 + ks * 32);
#pragma unroll
            for (int p = 0; p < 4; p++) {
                mma16816(C[2 * p],     aH[ks], bf[p][0], bf[p][1]);
                mma16816(C[2 * p + 1], aH[ks], bf[p][2], bf[p][3]);
            }
#pragma unroll
            for (int p = 0; p < 4; p++) {
                mma16816(C[2 * p],     aL[ks], bf[p][0], bf[p][1]);
                mma16816(C[2 * p + 1], aL[ks], bf[p][2], bf[p][3]);
            }
#pragma unroll
            for (int p = 0; p < 4; p++)
                ldsm4(bf[p][0], bf[p][1], bf[p][2], bf[p][3],
                      baseL + p * 1280 + ks * 32);
#pragma unroll
            for (int p = 0; p < 4; p++) {
                mma16816(C[2 * p],     aH[ks], bf[p][0], bf[p][1]);
                mma16816(C[2 * p + 1], aH[ks], bf[p][2], bf[p][3]);
            }
        }
    }

    // ---- partial denominators (4-lane quads) ----
    part_g  += __shfl_xor_sync(0xffffffffu, part_g, 1);
    part_g  += __shfl_xor_sync(0xffffffffu, part_g, 2);
    part_g8 += __shfl_xor_sync(0xffffffffu, part_g8, 1);
    part_g8 += __shfl_xor_sync(0xffffffffu, part_g8, 2);
    size_t growb = (size_t)b * NN + i0 + ilg;
    if (t == 0) {
        g_pd[(size_t)jh * (B * NN) + growb]     = part_g;
        g_pd[(size_t)jh * (B * NN) + growb + 8] = part_g8;
    }

    // ---- store partial C ----
    float* pc = g_pC + ((size_t)jh * (B * NN) + growb) * FOUT + 2 * t;
#pragma unroll
    for (int ns = 0; ns < 8; ns++) {
        *(float2*)(pc + 8 * ns)       = make_float2(C[ns][0], C[ns][1]);
        *(float2*)(pc + 8 * ns + 512) = make_float2(C[ns][2], C[ns][3]);
    }
}

// ---------------------------------------------------------------------------
// Kernel 3: combine halves + normalize. 4 threads/row, 8 LDG.128 upfront.
// ---------------------------------------------------------------------------
__global__ __launch_bounds__(256) void combine_kernel(float* __restrict__ out) {
    int gid = blockIdx.x * 256 + threadIdx.x;      // 65536
    int row = gid >> 2;
    int q   = (gid & 3) * 16;
    const float* p0 = g_pC + (size_t)row * FOUT + q;
    const float* p1 = g_pC + (size_t)(B * NN + row) * FOUT + q;
    float4 a0 = *(const float4*)p0;
    float4 a1 = *(const float4*)(p0 + 4);
    float4 a2 = *(const float4*)(p0 + 8);
    float4 a3 = *(const float4*)(p0 + 12);
    float4 b0 = *(const float4*)p1;
    float4 b1 = *(const float4*)(p1 + 4);
    float4 b2 = *(const float4*)(p1 + 8);
    float4 b3 = *(const float4*)(p1 + 12);
    float  d0 = g_pd[row];
    float  d1 = g_pd[B * NN + row];
    float inv = __fdividef(1.0f, d0 + d1);
    float* op = out + (size_t)row * FOUT + q;
    *(float4*)(op)      = make_float4((a0.x + b0.x) * inv, (a0.y + b0.y) * inv,
                                      (a0.z + b0.z) * inv, (a0.w + b0.w) * inv);
    *(float4*)(op + 4)  = make_float4((a1.x + b1.x) * inv, (a1.y + b1.y) * inv,
                                      (a1.z + b1.z) * inv, (a1.w + b1.w) * inv);
    *(float4*)(op + 8)  = make_float4((a2.x + b2.x) * inv, (a2.y + b2.y) * inv,
                                      (a2.z + b2.z) * inv, (a2.w + b2.w) * inv);
    *(float4*)(op + 12) = make_float4((a3.x + b3.x) * inv, (a3.y + b3.y) * inv,
                                      (a3.z + b3.z) * inv, (a3.w + b3.w) * inv);
}

// ---------------------------------------------------------------------------
extern "C" void kernel_launch(void* const* d_in, const int* in_sizes, int n_in,
                              void* d_out, int out_size) {
    const float* h   = (const float*)d_in[0];
    const int*   adj = (const int*)d_in[1];
    const float* W   = (const float*)d_in[2];
    const float* a   = (const float*)d_in[3];
    float* out = (float*)d_out;

    static int smem_set = 0;
    if (!smem_set) {
        cudaFuncSetAttribute(attn_kernel,
                             cudaFuncAttributeMaxDynamicSharedMemorySize, P_TOTAL);
        smem_set = 1;
    }

    wh_kernel<<<(B * NN) / 32, 256>>>(h, W, a);
    attn_kernel<<<dim3(NN / 64, B, 2), 128, P_TOTAL>>>(adj);
    combine_kernel<<<(B * NN * 4) / 256, 256>>>(out);
}

// round 16
// speedup vs baseline: 1.1518x; 1.1518x over previous
#include <cuda_runtime.h>
#include <cuda_bf16.h>
#include <cstdint>

#define B    8
#define NN   2048
#define FIN  128
#define FOUT 64

// Scratch (no cudaMalloc allowed)
__device__ __align__(16) __nv_bfloat16 g_Vth[B * FOUT * NN];  // [b][n][j] hi
__device__ __align__(16) __nv_bfloat16 g_Vtl[B * FOUT * NN];  // [b][n][j] lo
__device__ __align__(16) float    g_s1[B * NN];
__device__ __align__(16) float    g_s2[B * NN];
__device__ __align__(16) float2   g_e1[B * NN];               // (exp(s1), exp(.2 s1))
__device__ __align__(16) float2   g_e2[B * NN];               // (exp(s2), exp(.2 s2))
__device__ __align__(16) float    g_pC[2 * B * NN * FOUT];    // partial C
__device__ __align__(16) float    g_pd[2 * B * NN];           // partial denom

// ---------------------------------------------------------------------------
__device__ __forceinline__ float fexp(float x) {   // FMA-pipe exp, rel ~2e-6
    float z  = fmaf(x, 1.4426950408889634f, 12582912.0f);
    int   n  = __float_as_int(z) - 0x4B400000;
    float zf = z - 12582912.0f;
    float r  = fmaf(zf, -0.6931471805599453f, x);
    float p  =        1.3888889e-3f;
    p = fmaf(p, r,    8.3333333e-3f);
    p = fmaf(p, r,    4.1666668e-2f);
    p = fmaf(p, r,    1.6666667e-1f);
    p = fmaf(p, r,    5.0000000e-1f);
    p = fmaf(p, r,    1.0f);
    p = fmaf(p, r,    1.0f);
    return __int_as_float(__float_as_int(p) + (n << 23));
}

__device__ __forceinline__ uint32_t b2u(__nv_bfloat162 v) {
    return *reinterpret_cast<uint32_t*>(&v);
}
__device__ __forceinline__ void split2(float x0, float x1,
                                       uint32_t& hi, uint32_t& lo) {
    __nv_bfloat162 h = __floats2bfloat162_rn(x0, x1);
    float r0 = x0 - __bfloat162float(h.x);
    float r1 = x1 - __bfloat162float(h.y);
    hi = b2u(h);
    lo = b2u(__floats2bfloat162_rn(r0, r1));
}
__device__ __forceinline__ void splitT(float p0, float p1,
                                       uint32_t& hi, uint32_t& lo) {
    uint32_t i0 = __float_as_uint(p0), i1 = __float_as_uint(p1);
    float r0 = p0 - __uint_as_float(i0 & 0xffff0000u);
    float r1 = p1 - __uint_as_float(i1 & 0xffff0000u);
    asm("prmt.b32 %0, %1, %2, 0x7632;" : "=r"(hi) : "r"(i0), "r"(i1));
    lo = b2u(__floats2bfloat162_rn(r0, r1));
}
// adj-independent p candidate (sign select only; mask applied post-wait)
__device__ __forceinline__ float pval(float s1, float e1p, float e1n,
                                      float s2, float e2p, float e2n) {
    float t = s1 + s2;
    return (t > 0.f) ? e1p * e2p : e1n * e2n;
}
__device__ __forceinline__ void mma16816(float* c, const uint32_t* a,
                                         uint32_t b0, uint32_t b1) {
    asm volatile(
        "mma.sync.aligned.m16n8k16.row.col.f32.bf16.bf16.f32 "
        "{%0,%1,%2,%3}, {%4,%5,%6,%7}, {%8,%9}, {%0,%1,%2,%3};"
        : "+f"(c[0]), "+f"(c[1]), "+f"(c[2]), "+f"(c[3])
        : "r"(a[0]), "r"(a[1]), "r"(a[2]), "r"(a[3]), "r"(b0), "r"(b1));
}
__device__ __forceinline__ void ldsm4(uint32_t& r0, uint32_t& r1,
                                      uint32_t& r2, uint32_t& r3, uint32_t a) {
    asm volatile("ldmatrix.sync.aligned.m8n8.x4.shared.b16 {%0,%1,%2,%3}, [%4];"
                 : "=r"(r0), "=r"(r1), "=r"(r2), "=r"(r3) : "r"(a));
}
__device__ __forceinline__ uint32_t smem_u32(const void* p) {
    uint32_t a;
    asm("{ .reg .u64 t; cvta.to.shared.u64 t, %1; cvt.u32.u64 %0, t; }"
        : "=r"(a) : "l"(p));
    return a;
}
#define CP16(dst, src) asm volatile("cp.async.cg.shared.global [%0], [%1], 16;" :: "r"(dst), "l"(src) : "memory")
#define CP_COMMIT()    asm volatile("cp.async.commit_group;" ::: "memory")
#define CP_WAIT0()     asm volatile("cp.async.wait_group 0;" ::: "memory")

// ---------------------------------------------------------------------------
// Kernel 1: Wh = h @ W^T, fused s1/s2 (+ exp tables), transposed bf16 hi/lo V.
// (unchanged — protect)
// ---------------------------------------------------------------------------
__global__ __launch_bounds__(256) void wh_kernel(const float* __restrict__ h,
                                                 const float* __restrict__ W,
                                                 const float* __restrict__ a) {
    __shared__ float Wt[FIN][68];
    __shared__ float Tr[64][33];
    int tid = threadIdx.x;
    for (int idx = tid; idx < FOUT * FIN; idx += 256) {
        int o = idx >> 7, f = idx & 127;
        Wt[f][o] = W[idx];
    }
    __syncthreads();

    int row0 = blockIdx.x * 32;
    int rg = tid >> 4, cg = tid & 15;
    int r0 = row0 + rg * 2;
    int c0 = cg * 4;

    float acc[2][4] = {};
    const float* hp = h + (size_t)r0 * FIN;
    float4 hc0 = __ldg((const float4*)hp);
    float4 hc1 = __ldg((const float4*)(hp + FIN));
#pragma unroll 4
    for (int f = 0; f < FIN; f += 4) {
        float4 hn0, hn1;
        if (f + 4 < FIN) {
            hn0 = __ldg((const float4*)(hp + f + 4));
            hn1 = __ldg((const float4*)(hp + FIN + f + 4));
        }
        float4 wv0 = *(const float4*)&Wt[f + 0][c0];
        float4 wv1 = *(const float4*)&Wt[f + 1][c0];
        float4 wv2 = *(const float4*)&Wt[f + 2][c0];
        float4 wv3 = *(const float4*)&Wt[f + 3][c0];
        acc[0][0] += hc0.x * wv0.x + hc0.y * wv1.x + hc0.z * wv2.x + hc0.w * wv3.x;
        acc[0][1] += hc0.x * wv0.y + hc0.y * wv1.y + hc0.z * wv2.y + hc0.w * wv3.y;
        acc[0][2] += hc0.x * wv0.z + hc0.y * wv1.z + hc0.z * wv2.z + hc0.w * wv3.z;
        acc[0][3] += hc0.x * wv0.w + hc0.y * wv1.w + hc0.z * wv2.w + hc0.w * wv3.w;
        acc[1][0] += hc1.x * wv0.x + hc1.y * wv1.x + hc1.z * wv2.x + hc1.w * wv3.x;
        acc[1][1] += hc1.x * wv0.y + hc1.y * wv1.y + hc1.z * wv2.y + hc1.w * wv3.y;
        acc[1][2] += hc1.x * wv0.z + hc1.y * wv1.z + hc1.z * wv2.z + hc1.w * wv3.z;
        acc[1][3] += hc1.x * wv0.w + hc1.y * wv1.w + hc1.z * wv2.w + hc1.w * wv3.w;
        hc0 = hn0; hc1 = hn1;
    }
    __syncthreads();

    float a1x = __ldg(&a[c0]),          a1y = __ldg(&a[c0 + 1]);
    float a1z = __ldg(&a[c0 + 2]),      a1w = __ldg(&a[c0 + 3]);
    float a2x = __ldg(&a[64 + c0]),     a2y = __ldg(&a[64 + c0 + 1]);
    float a2z = __ldg(&a[64 + c0 + 2]), a2w = __ldg(&a[64 + c0 + 3]);

#pragma unroll
    for (int k = 0; k < 2; k++) {
        float t1 = acc[k][0] * a1x + acc[k][1] * a1y + acc[k][2] * a1z + acc[k][3] * a1w;
        float t2 = acc[k][0] * a2x + acc[k][1] * a2y + acc[k][2] * a2z + acc[k][3] * a2w;
#pragma unroll
        for (int ofs = 8; ofs >= 1; ofs >>= 1) {
            t1 += __shfl_xor_sync(0xffffffffu, t1, ofs);
            t2 += __shfl_xor_sync(0xffffffffu, t2, ofs);
        }
        if (cg == 0) {
            g_s1[r0 + k] = t1;
            g_s2[r0 + k] = t2;
            g_e1[r0 + k] = make_float2(fexp(t1), fexp(0.2f * t1));
            g_e2[r0 + k] = make_float2(fexp(t2), fexp(0.2f * t2));
        }
#pragma unroll
        for (int q = 0; q < 4; q++) Tr[c0 + q][rg * 2 + k] = acc[k][q];
    }
    __syncthreads();

    {
        int c  = tid >> 2;
        int jl = (tid & 3) * 8;
        int bb = row0 >> 11;
        int jb = row0 & 2047;
        float v[8];
#pragma unroll
        for (int q = 0; q < 8; q++) v[q] = Tr[c][jl + q];
        uint32_t hu[4], lu[4];
#pragma unroll
        for (int q = 0; q < 4; q++)
            split2(v[2 * q], v[2 * q + 1], hu[q], lu[q]);
        size_t dst = ((size_t)bb * 64 + c) * NN + jb + jl;
        *(uint4*)(g_Vth + dst) = make_uint4(hu[0], hu[1], hu[2], hu[3]);
        *(uint4*)(g_Vtl + dst) = make_uint4(lu[0], lu[1], lu[2], lu[3]);
    }
}

// ---------------------------------------------------------------------------
// Kernel 2: attention partial (round-14 config: 32-j tiles, 2-deep cp.async,
// smem tables, 4 CTAs/SM). NEW: the adj-independent p-candidates are computed
// BEFORE cp.async.wait (the asm memory clobber otherwise blocks hoisting) —
// only mask-select + splitT + MMA remain on the post-wait critical path.
// ---------------------------------------------------------------------------
#define NVH(buf)  ((buf) * 5120)               // 64 x 80B
#define NVL(buf)  (10240 + (buf) * 5120)
#define NADJ(buf) (20480 + (buf) * 9216)       // 64 x 144B
#define N_E2      38912                        // float2[1024]
#define N_S2      47104                        // float[1024]
#define N_TOTAL   51200

__global__ __launch_bounds__(128, 4) void attn_kernel(const int* __restrict__ adj) {
    extern __shared__ __align__(16) char sm[];
    float* sE2 = (float*)(sm + N_E2);
    float* sS2 = (float*)(sm + N_S2);
    uint32_t sb = smem_u32(sm);

    int tid  = threadIdx.x;
    int w    = tid >> 5;
    int lane = tid & 31;
    int g    = lane >> 2;
    int t    = lane & 3;
    int b    = blockIdx.y;
    int i0   = blockIdx.x * 64;
    int jh   = blockIdx.z;

    // ---- preload e2/s2 tables ----
    {
        const float4* e2src = (const float4*)(g_e2 + b * NN + jh * 1024);
#pragma unroll
        for (int k = 0; k < 4; k++) ((float4*)sE2)[tid + k * 128] = e2src[tid + k * 128];
        const float4* s2src = (const float4*)(g_s2 + b * NN + jh * 1024);
#pragma unroll
        for (int k = 0; k < 2; k++) ((float4*)sS2)[tid + k * 128] = s2src[tid + k * 128];
    }

    int    ilg = w * 16 + g;
    float  s1g  = g_s1[b * NN + i0 + ilg];
    float  s1g8 = g_s1[b * NN + i0 + ilg + 8];
    float2 e1g  = g_e1[b * NN + i0 + ilg];
    float2 e1g8 = g_e1[b * NN + i0 + ilg + 8];

    const __nv_bfloat16* vhb = g_Vth + (size_t)b * 64 * NN + jh * 1024;
    const __nv_bfloat16* vlb = g_Vtl + (size_t)b * 64 * NN + jh * 1024;
    const int*           ajb = adj + ((size_t)(b * NN + i0)) * NN + jh * 1024;

    uint32_t lsm_off = (((lane >> 4) & 1) * 8 + (lane & 7)) * 80
                     + ((lane >> 3) & 1) * 16;

    float C[8][4] = {};
    float part_g = 0.f, part_g8 = 0.f;

    // ---- issue tile 0 ----
#pragma unroll
    for (int q = 0; q < 2; q++) {
        int c = tid + q * 128;
        int r = c >> 2, kc = c & 3;
        CP16(sb + NVH(0) + r * 80 + kc * 16, vhb + (size_t)r * NN + kc * 8);
        CP16(sb + NVL(0) + r * 80 + kc * 16, vlb + (size_t)r * NN + kc * 8);
    }
#pragma unroll
    for (int q = 0; q < 4; q++) {
        int c = tid + q * 128;
        int r = c >> 3, kc = c & 7;
        CP16(sb + NADJ(0) + r * 144 + kc * 16, ajb + (size_t)r * NN + kc * 4);
    }
    CP_COMMIT();
    __syncthreads();     // tables visible

    for (int it = 0; it < 32; ++it) {
        int buf = it & 1;
        int j0  = it * 32;

        // ==== PRE-WAIT: adj-independent p candidates from resident tables ====
        float pv[2][8];
#pragma unroll
        for (int ks = 0; ks < 2; ks++) {
            int jb = j0 + ks * 16 + 2 * t;
            float2 sA = *(const float2*)&sS2[jb];
            float2 sB = *(const float2*)&sS2[jb + 8];
            float4 eA = *(const float4*)&sE2[2 * jb];
            float4 eB = *(const float4*)&sE2[2 * (jb + 8)];
            pv[ks][0] = pval(s1g,  e1g.x,  e1g.y,  sA.x, eA.x, eA.y);
            pv[ks][1] = pval(s1g,  e1g.x,  e1g.y,  sA.y, eA.z, eA.w);
            pv[ks][2] = pval(s1g,  e1g.x,  e1g.y,  sB.x, eB.x, eB.y);
            pv[ks][3] = pval(s1g,  e1g.x,  e1g.y,  sB.y, eB.z, eB.w);
            pv[ks][4] = pval(s1g8, e1g8.x, e1g8.y, sA.x, eA.x, eA.y);
            pv[ks][5] = pval(s1g8, e1g8.x, e1g8.y, sA.y, eA.z, eA.w);
            pv[ks][6] = pval(s1g8, e1g8.x, e1g8.y, sB.x, eB.x, eB.y);
            pv[ks][7] = pval(s1g8, e1g8.x, e1g8.y, sB.y, eB.z, eB.w);
        }

        CP_WAIT0();               // tile it resident
        __syncthreads();

        // issue tile it+1 into the other buffer
        if (it + 1 < 32) {
            int jn = j0 + 32;
            int ob = 1 - buf;
#pragma unroll
            for (int q = 0; q < 2; q++) {
                int c = tid + q * 128;
                int r = c >> 2, kc = c & 3;
                CP16(sb + NVH(ob) + r * 80 + kc * 16, vhb + (size_t)r * NN + jn + kc * 8);
                CP16(sb + NVL(ob) + r * 80 + kc * 16, vlb + (size_t)r * NN + jn + kc * 8);
            }
#pragma unroll
            for (int q = 0; q < 4; q++) {
                int c = tid + q * 128;
                int r = c >> 3, kc = c & 7;
                CP16(sb + NADJ(ob) + r * 144 + kc * 16, ajb + (size_t)r * NN + jn + kc * 4);
            }
            CP_COMMIT();
        }

        // ==== POST-WAIT: mask select + denom + splitT ====
        uint32_t aH[2][4], aL[2][4];
        const char* ab = sm + NADJ(buf);
#pragma unroll
        for (int ks = 0; ks < 2; ks++) {
            int jl = ks * 16 + 2 * t;
            int2 m0 = *(const int2*)(ab + ilg * 144 + jl * 4);
            int2 m1 = *(const int2*)(ab + ilg * 144 + (jl + 8) * 4);
            int2 m2 = *(const int2*)(ab + (ilg + 8) * 144 + jl * 4);
            int2 m3 = *(const int2*)(ab + (ilg + 8) * 144 + (jl + 8) * 4);

            float p00 = m0.x ? pv[ks][0] : 0.f;
            float p01 = m0.y ? pv[ks][1] : 0.f;
            float p02 = m1.x ? pv[ks][2] : 0.f;
            float p03 = m1.y ? pv[ks][3] : 0.f;
            float p10 = m2.x ? pv[ks][4] : 0.f;
            float p11 = m2.y ? pv[ks][5] : 0.f;
            float p12 = m3.x ? pv[ks][6] : 0.f;
            float p13 = m3.y ? pv[ks][7] : 0.f;

            part_g  += (p00 + p01) + (p02 + p03);
            part_g8 += (p10 + p11) + (p12 + p13);

            splitT(p00, p01, aH[ks][0], aL[ks][0]);
            splitT(p10, p11, aH[ks][1], aL[ks][1]);
            splitT(p02, p03, aH[ks][2], aL[ks][2]);
            splitT(p12, p13, aH[ks][3], aL[ks][3]);
        }

        // ---- MMAs, term-major ----
        uint32_t baseH = sb + NVH(buf) + lsm_off;
        uint32_t baseL = sb + NVL(buf) + lsm_off;
#pragma unroll
        for (int ks = 0; ks < 2; ks++) {
            uint32_t bf[4][4];
#pragma unroll
            for (int p = 0; p < 4; p++)
                ldsm4(bf[p][0], bf[p][1], bf[p][2], bf[p][3],
                      baseH + p * 1280 + ks * 32);
#pragma unroll
            for (int p = 0; p < 4; p++) {
                mma16816(C[2 * p],     aH[ks], bf[p][0], bf[p][1]);
                mma16816(C[2 * p + 1], aH[ks], bf[p][2], bf[p][3]);
            }
#pragma unroll
            for (int p = 0; p < 4; p++) {
                mma16816(C[2 * p],     aL[ks], bf[p][0], bf[p][1]);
                mma16816(C[2 * p + 1], aL[ks], bf[p][2], bf[p][3]);
            }
#pragma unroll
            for (int p = 0; p < 4; p++)
                ldsm4(bf[p][0], bf[p][1], bf[p][2], bf[p][3],
                      baseL + p * 1280 + ks * 32);
#pragma unroll
            for (int p = 0; p < 4; p++) {
                mma16816(C[2 * p],     aH[ks], bf[p][0], bf[p][1]);
                mma16816(C[2 * p + 1], aH[ks], bf[p][2], bf[p][3]);
            }
        }
    }

    // ---- partial denominators (4-lane quads) ----
    part_g  += __shfl_xor_sync(0xffffffffu, part_g, 1);
    part_g  += __shfl_xor_sync(0xffffffffu, part_g, 2);
    part_g8 += __shfl_xor_sync(0xffffffffu, part_g8, 1);
    part_g8 += __shfl_xor_sync(0xffffffffu, part_g8, 2);
    size_t growb = (size_t)b * NN + i0 + ilg;
    if (t == 0) {
        g_pd[(size_t)jh * (B * NN) + growb]     = part_g;
        g_pd[(size_t)jh * (B * NN) + growb + 8] = part_g8;
    }

    // ---- store partial C ----
    float* pc = g_pC + ((size_t)jh * (B * NN) + growb) * FOUT + 2 * t;
#pragma unroll
    for (int ns = 0; ns < 8; ns++) {
        *(float2*)(pc + 8 * ns)       = make_float2(C[ns][0], C[ns][1]);
        *(float2*)(pc + 8 * ns + 512) = make_float2(C[ns][2], C[ns][3]);
    }
}

// ---------------------------------------------------------------------------
// Kernel 3: combine halves + normalize. 4 threads/row, 8 LDG.128 upfront.
// ---------------------------------------------------------------------------
__global__ __launch_bounds__(256) void combine_kernel(float* __restrict__ out) {
    int gid = blockIdx.x * 256 + threadIdx.x;      // 65536
    int row = gid >> 2;
    int q   = (gid & 3) * 16;
    const float* p0 = g_pC + (size_t)row * FOUT + q;
    const float* p1 = g_pC + (size_t)(B * NN + row) * FOUT + q;
    float4 a0 = *(const float4*)p0;
    float4 a1 = *(const float4*)(p0 + 4);
    float4 a2 = *(const float4*)(p0 + 8);
    float4 a3 = *(const float4*)(p0 + 12);
    float4 b0 = *(const float4*)p1;
    float4 b1 = *(const float4*)(p1 + 4);
    float4 b2 = *(const float4*)(p1 + 8);
    float4 b3 = *(const float4*)(p1 + 12);
    float  d0 = g_pd[row];
    float  d1 = g_pd[B * NN + row];
    float inv = __fdividef(1.0f, d0 + d1);
    float* op = out + (size_t)row * FOUT + q;
    *(float4*)(op)      = make_float4((a0.x + b0.x) * inv, (a0.y + b0.y) * inv,
                                      (a0.z + b0.z) * inv, (a0.w + b0.w) * inv);
    *(float4*)(op + 4)  = make_float4((a1.x + b1.x) * inv, (a1.y + b1.y) * inv,
                                      (a1.z + b1.z) * inv, (a1.w + b1.w) * inv);
    *(float4*)(op + 8)  = make_float4((a2.x + b2.x) * inv, (a2.y + b2.y) * inv,
                                      (a2.z + b2.z) * inv, (a2.w + b2.w) * inv);
    *(float4*)(op + 12) = make_float4((a3.x + b3.x) * inv, (a3.y + b3.y) * inv,
                                      (a3.z + b3.z) * inv, (a3.w + b3.w) * inv);
}

// ---------------------------------------------------------------------------
extern "C" void kernel_launch(void* const* d_in, const int* in_sizes, int n_in,
                              void* d_out, int out_size) {
    const float* h   = (const float*)d_in[0];
    const int*   adj = (const int*)d_in[1];
    const float* W   = (const float*)d_in[2];
    const float* a   = (const float*)d_in[3];
    float* out = (float*)d_out;

    static int smem_set = 0;
    if (!smem_set) {
        cudaFuncSetAttribute(attn_kernel,
                             cudaFuncAttributeMaxDynamicSharedMemorySize, N_TOTAL);
        smem_set = 1;
    }

    wh_kernel<<<(B * NN) / 32, 256>>>(h, W, a);
    attn_kernel<<<dim3(NN / 64, B, 2), 128, N_TOTAL>>>(adj);
    combine_kernel<<<(B * NN * 4) / 256, 256>>>(out);
}